// round 15
// baseline (speedup 1.0000x reference)
#include <cuda_runtime.h>
#include <math.h>

#define BB 64
#define NN 17
#define CC 32
#define HW 4096   // 64*64

#define OFF_J 0           // joints: 64*17*2 = 2176
#define OFF_V 2176        // valid:  64*17   = 1088
#define OFF_K 3264        // new_keys: 64*17*32 = 34816
#define OFF_D 38080       // dist_x4: 64*17*256*256 = 71303168

#define NBATCH 4
#define BPB (BB / NBATCH)          // 16 b per batch

__device__ float g_wdist[(size_t)BB * NN * HW];

// Proven-equal closed form of the 15-move ring weight (validated rounds 11-14)
__device__ __forceinline__ float weight_at(int x, int y, int kx, int ky) {
    int dx = abs(x - kx), dy = abs(y - ky);
    int M = max(dx, dy);
    bool border = (kx == 0) | (kx == 63) | (ky == 0) | (ky == 63);
    if (M == 0) return border ? 0.75f : 10.0f;
    return (M <= 15) ? fmaf(0.25f, (float)M, 0.5f) : 10.0f;
}

// ---------------- Kernel A: wdist (round-14 exact, + batch offset) --------
__global__ void __launch_bounds__(512) kA(const float* __restrict__ q,
                                          const float* __restrict__ keys,
                                          const int*   __restrict__ joints,
                                          int b0) {
    const int b = blockIdx.y + b0;
    const int p = blockIdx.x * 512 + threadIdx.x;
    __shared__ __align__(16) float skey[NN][CC];
    __shared__ float sk2[NN];
    __shared__ int   skx[NN], sky[NN];
    const int t = threadIdx.x;
    if (t < NN * CC / 4)
        reinterpret_cast<float4*>(skey)[t] =
            reinterpret_cast<const float4*>(keys + b * NN * CC)[t];
    __syncthreads();
    if (t < NN) {
        float s = 0.f;   // mul+add sequential, no fma (XLA-faithful)
        for (int c = 0; c < CC; c++) s = __fadd_rn(s, __fmul_rn(skey[t][c], skey[t][c]));
        sk2[t] = s;
        skx[t] = joints[(b * NN + t) * 2 + 0];
        sky[t] = joints[(b * NN + t) * 2 + 1];
    }
    __syncthreads();

    float qv[CC];
    const float* qb = q + (size_t)b * CC * HW + p;
    float q2 = 0.f;
#pragma unroll
    for (int c = 0; c < CC; c++) {
        qv[c] = qb[(size_t)c * HW];
        q2 = __fadd_rn(q2, __fmul_rn(qv[c], qv[c]));
    }

    const int y = p >> 6, x = p & 63;
    float* wout = g_wdist + ((size_t)b * NN) * HW + p;
#pragma unroll 2
    for (int n = 0; n < NN; n++) {
        const float4* k4 = reinterpret_cast<const float4*>(skey[n]);
        float dot = 0.f;   // sequential ascending-c fmaf (gemm-faithful)
#pragma unroll
        for (int c4 = 0; c4 < CC / 4; c4++) {
            float4 kk = k4[c4];
            dot = fmaf(kk.x, qv[4 * c4 + 0], dot);
            dot = fmaf(kk.y, qv[4 * c4 + 1], dot);
            dot = fmaf(kk.z, qv[4 * c4 + 2], dot);
            dot = fmaf(kk.w, qv[4 * c4 + 3], dot);
        }
        float d2 = __fsub_rn(__fadd_rn(q2, sk2[n]), __fmul_rn(2.0f, dot));
        float dist = sqrtf(fmaxf(d2, 0.0f));
        float wm = weight_at(x, y, skx[n], sky[n]);
        wout[(size_t)n * HW] = __fmul_rn(dist, wm);
    }
}

// ---------------- Kernel B (round-14 exact, + batch offset) ---------------
__global__ void __launch_bounds__(256, 8) kB(const float* __restrict__ q,
                                             const float* __restrict__ keys,
                                             float* __restrict__ out,
                                             int bn0) {
    const int bn = blockIdx.x + bn0;
    const int b  = bn / NN;
    const int t  = threadIdx.x;

    __shared__ float sw[64 * 64];
    __shared__ float rv[256];
    __shared__ int   ri[256];
    __shared__ int   s_valid;

    // phase 1: load wdist, per-thread min/argmin (reduction deferred)
    const float* src = g_wdist + (size_t)bn * HW;
    float bv = 3.0e38f; int bi = 0;
    for (int k = 0; k < 16; k++) {
        int idx = k * 256 + t;          // ascending per-thread -> strict <
        float v = src[idx];
        sw[idx] = v;
        if (v < bv) { bv = v; bi = idx; }
    }
    __syncthreads();

    // phase 2: 4x bilinear upsample, gemm-faithful scalar arithmetic
    float* od = out + OFF_D + (size_t)bn * 65536;
    float bv2 = 3.0e38f; int bi2 = 0;
    for (int it = 0; it < 16; it++) {
        int T = it * 256 + t;
        int ti = T >> 6, tj = T & 63;
        int yU = (ti > 0) ? ti - 1 : 0;
        int yD = (ti < 63) ? ti + 1 : 63;
        int xL = (tj > 0) ? tj - 1 : 0;
        int xR = (tj < 63) ? tj + 1 : 63;

        float up[3] = { sw[yU * 64 + xL], sw[yU * 64 + tj], sw[yU * 64 + xR] };
        float ce[3] = { sw[ti * 64 + xL], sw[ti * 64 + tj], sw[ti * 64 + xR] };
        float dn[3] = { sw[yD * 64 + xL], sw[yD * 64 + tj], sw[yD * 64 + xR] };

        float vy[4][3];
#pragma unroll
        for (int c3 = 0; c3 < 3; c3++) {
            if (ti == 0) { vy[0][c3] = ce[c3]; vy[1][c3] = ce[c3]; }
            else {
                vy[0][c3] = fmaf(0.625f, ce[c3], __fmul_rn(0.375f, up[c3]));
                vy[1][c3] = fmaf(0.875f, ce[c3], __fmul_rn(0.125f, up[c3]));
            }
            if (ti == 63) { vy[2][c3] = ce[c3]; vy[3][c3] = ce[c3]; }
            else {
                vy[2][c3] = fmaf(0.125f, dn[c3], __fmul_rn(0.875f, ce[c3]));
                vy[3][c3] = fmaf(0.375f, dn[c3], __fmul_rn(0.625f, ce[c3]));
            }
        }
#pragma unroll
        for (int r = 0; r < 4; r++) {
            float vL = vy[r][0], vC = vy[r][1], vR = vy[r][2];
            float o0, o1, o2, o3;
            if (tj == 0) { o0 = vC; o1 = vC; }
            else {
                o0 = fmaf(0.625f, vC, __fmul_rn(0.375f, vL));
                o1 = fmaf(0.875f, vC, __fmul_rn(0.125f, vL));
            }
            if (tj == 63) { o2 = vC; o3 = vC; }
            else {
                o2 = fmaf(0.125f, vR, __fmul_rn(0.875f, vC));
                o3 = fmaf(0.375f, vR, __fmul_rn(0.625f, vC));
            }
            int pbase = (4 * ti + r) * 256 + 4 * tj;
            *reinterpret_cast<float4*>(od + pbase) = make_float4(o0, o1, o2, o3);
            if (o0 < bv2) { bv2 = o0; bi2 = pbase; }
            if (o1 < bv2) { bv2 = o1; bi2 = pbase + 1; }
            if (o2 < bv2) { bv2 = o2; bi2 = pbase + 2; }
            if (o3 < bv2) { bv2 = o3; bi2 = pbase + 3; }
        }
    }

    // deferred reduction 1 (wdist)
    __syncthreads();
    rv[t] = bv; ri[t] = bi;
    __syncthreads();
    for (int s = 128; s > 0; s >>= 1) {
        if (t < s) {
            float v2 = rv[t + s]; int i2 = ri[t + s];
            if (v2 < rv[t] || (v2 == rv[t] && i2 < ri[t])) { rv[t] = v2; ri[t] = i2; }
        }
        __syncthreads();
    }
    const float gmin1 = rv[0];
    const int   idx1  = ri[0];
    __syncthreads();

    // deferred reduction 2 (dist_x4)
    rv[t] = bv2; ri[t] = bi2;
    __syncthreads();
    for (int s = 128; s > 0; s >>= 1) {
        if (t < s) {
            float v2 = rv[t + s]; int i2 = ri[t + s];
            if (v2 < rv[t] || (v2 == rv[t] && i2 < ri[t])) { rv[t] = v2; ri[t] = i2; }
        }
        __syncthreads();
    }

    if (t == 0) {
        int sidx = ri[0];
        bool nonzero = false;
        for (int c = 0; c < CC; c++) nonzero |= (keys[bn * CC + c] != 0.0f);
        bool valid = nonzero && ((int)floorf(gmin1) <= 5);
        s_valid = valid ? 1 : 0;
        int sv = valid ? (sidx >> 8)  : -1;
        int sh = valid ? (sidx & 255) : -1;
        out[OFF_J + bn * 2 + 0] = (float)sv;
        out[OFF_J + bn * 2 + 1] = (float)sh;
        out[OFF_V + bn] = valid ? 1.0f : 0.0f;
    }
    __syncthreads();
    if (t < CC) {
        float nk = s_valid ? q[((size_t)b * CC + t) * HW + idx1]
                           : keys[bn * CC + t];
        out[OFF_K + bn * CC + t] = nk;
    }
}

extern "C" void kernel_launch(void* const* d_in, const int* in_sizes, int n_in,
                              void* d_out, int out_size) {
    const float* q      = (const float*)d_in[0];
    const float* keys   = (const float*)d_in[1];
    const int*   joints = (const int*)  d_in[2];
    float* out = (float*)d_out;

    // One side stream + events, created once (no device memory involved).
    static cudaStream_t s1 = nullptr;
    static cudaEvent_t  evFork = nullptr;
    static cudaEvent_t  evA[NBATCH - 1];
    if (s1 == nullptr) {
        cudaStreamCreateWithFlags(&s1, cudaStreamNonBlocking);
        cudaEventCreateWithFlags(&evFork, cudaEventDisableTiming);
        for (int i = 0; i < NBATCH - 1; i++)
            cudaEventCreateWithFlags(&evA[i], cudaEventDisableTiming);
    }

    dim3 gA(8, BPB);                   // 128 blocks per batch
    const int kbPerBatch = BPB * NN;   // 272 blocks per batch

    // batch 0 wdist on main stream
    kA<<<gA, 512>>>(q, keys, joints, 0);

    // fork: remaining wdist batches on side stream
    cudaEventRecord(evFork, 0);
    cudaStreamWaitEvent(s1, evFork, 0);
    for (int i = 1; i < NBATCH; i++) {
        kA<<<gA, 512, 0, s1>>>(q, keys, joints, i * BPB);
        cudaEventRecord(evA[i - 1], s1);
    }

    // kB batches on main stream, each gated on its producer
    kB<<<kbPerBatch, 256>>>(q, keys, out, 0);
    for (int i = 1; i < NBATCH; i++) {
        cudaStreamWaitEvent(0, evA[i - 1], 0);
        kB<<<kbPerBatch, 256>>>(q, keys, out, i * kbPerBatch);
    }
}

// round 16
// speedup vs baseline: 1.2333x; 1.2333x over previous
#include <cuda_runtime.h>
#include <math.h>

#define BB 64
#define NN 17
#define CC 32
#define HW 4096   // 64*64

#define OFF_J 0           // joints: 64*17*2 = 2176
#define OFF_V 2176        // valid:  64*17   = 1088
#define OFF_K 3264        // new_keys: 64*17*32 = 34816
#define OFF_D 38080       // dist_x4: 64*17*256*256 = 71303168

__device__ float g_wdist[(size_t)BB * NN * HW];
// mid-chain partials (c = 0..15 prefix), L2-resident
__device__ float g_pdot[(size_t)BB * NN * HW];   // 17.8 MB
__device__ float g_pq2[(size_t)BB * HW];         // 1 MB

// Proven-equal closed form of the 15-move ring weight (validated rounds 11-14)
__device__ __forceinline__ float weight_at(int x, int y, int kx, int ky) {
    int dx = abs(x - kx), dy = abs(y - ky);
    int M = max(dx, dy);
    bool border = (kx == 0) | (kx == 63) | (ky == 0) | (ky == 63);
    if (M == 0) return border ? 0.75f : 10.0f;
    return (M <= 15) ? fmaf(0.25f, (float)M, 0.5f) : 10.0f;
}

// ---------------- Kernel A pass 1: chain prefix c = 0..15 ----------------
__global__ void __launch_bounds__(256) kA1(const float* __restrict__ q,
                                           const float* __restrict__ keys) {
    const int b = blockIdx.y;
    const int p = blockIdx.x * 256 + threadIdx.x;
    __shared__ __align__(16) float skey[NN][CC];
    const int t = threadIdx.x;
    if (t < NN * CC / 4)
        reinterpret_cast<float4*>(skey)[t] =
            reinterpret_cast<const float4*>(keys + b * NN * CC)[t];
    __syncthreads();

    float qv[16];
    const float* qb = q + (size_t)b * CC * HW + p;
    float q2 = 0.f;
#pragma unroll
    for (int c = 0; c < 16; c++) {
        qv[c] = qb[(size_t)c * HW];
        q2 = __fadd_rn(q2, __fmul_rn(qv[c], qv[c]));   // ascending c, mul+add
    }
    g_pq2[(size_t)b * HW + p] = q2;

    float* pout = g_pdot + ((size_t)b * NN) * HW + p;
#pragma unroll 2
    for (int n = 0; n < NN; n++) {
        const float4* k4 = reinterpret_cast<const float4*>(skey[n]);
        float dot = 0.f;   // ascending-c fmaf chain, c = 0..15
#pragma unroll
        for (int c4 = 0; c4 < 4; c4++) {
            float4 kk = k4[c4];
            dot = fmaf(kk.x, qv[4 * c4 + 0], dot);
            dot = fmaf(kk.y, qv[4 * c4 + 1], dot);
            dot = fmaf(kk.z, qv[4 * c4 + 2], dot);
            dot = fmaf(kk.w, qv[4 * c4 + 3], dot);
        }
        pout[(size_t)n * HW] = dot;    // exact mid-chain rounding state
    }
}

// ---------------- Kernel A pass 2: continue chain c = 16..31 --------------
__global__ void __launch_bounds__(256) kA2(const float* __restrict__ q,
                                           const float* __restrict__ keys,
                                           const int*   __restrict__ joints) {
    const int b = blockIdx.y;
    const int p = blockIdx.x * 256 + threadIdx.x;
    __shared__ __align__(16) float skey[NN][CC];
    __shared__ float sk2[NN];
    __shared__ int   skx[NN], sky[NN];
    const int t = threadIdx.x;
    if (t < NN * CC / 4)
        reinterpret_cast<float4*>(skey)[t] =
            reinterpret_cast<const float4*>(keys + b * NN * CC)[t];
    __syncthreads();
    if (t < NN) {
        float s = 0.f;   // mul+add sequential over all 32 c (XLA-faithful)
        for (int c = 0; c < CC; c++) s = __fadd_rn(s, __fmul_rn(skey[t][c], skey[t][c]));
        sk2[t] = s;
        skx[t] = joints[(b * NN + t) * 2 + 0];
        sky[t] = joints[(b * NN + t) * 2 + 1];
    }
    __syncthreads();

    float qv[16];
    const float* qb = q + (size_t)b * CC * HW + p;
    float q2 = g_pq2[(size_t)b * HW + p];          // chain state after c=15
#pragma unroll
    for (int c = 0; c < 16; c++) {
        qv[c] = qb[(size_t)(16 + c) * HW];
        q2 = __fadd_rn(q2, __fmul_rn(qv[c], qv[c]));   // continue c=16..31
    }

    const int y = p >> 6, x = p & 63;
    const float* pin = g_pdot + ((size_t)b * NN) * HW + p;
    float* wout = g_wdist + ((size_t)b * NN) * HW + p;
#pragma unroll 2
    for (int n = 0; n < NN; n++) {
        const float4* k4 = reinterpret_cast<const float4*>(skey[n] + 16);
        float dot = pin[(size_t)n * HW];           // chain state after c=15
#pragma unroll
        for (int c4 = 0; c4 < 4; c4++) {
            float4 kk = k4[c4];
            dot = fmaf(kk.x, qv[4 * c4 + 0], dot);
            dot = fmaf(kk.y, qv[4 * c4 + 1], dot);
            dot = fmaf(kk.z, qv[4 * c4 + 2], dot);
            dot = fmaf(kk.w, qv[4 * c4 + 3], dot);
        }
        float d2 = __fsub_rn(__fadd_rn(q2, sk2[n]), __fmul_rn(2.0f, dot));
        float dist = sqrtf(fmaxf(d2, 0.0f));
        float wm = weight_at(x, y, skx[n], sky[n]);
        wout[(size_t)n * HW] = __fmul_rn(dist, wm);
    }
}

// ---------------- Kernel B (round-14 exact) ----------------
__global__ void __launch_bounds__(256, 8) kB(const float* __restrict__ q,
                                             const float* __restrict__ keys,
                                             float* __restrict__ out) {
    const int bn = blockIdx.x;          // b*17+n
    const int b  = bn / NN;
    const int t  = threadIdx.x;

    __shared__ float sw[64 * 64];
    __shared__ float rv[256];
    __shared__ int   ri[256];
    __shared__ int   s_valid;

    // phase 1: load wdist, per-thread min/argmin (reduction deferred)
    const float* src = g_wdist + (size_t)bn * HW;
    float bv = 3.0e38f; int bi = 0;
    for (int k = 0; k < 16; k++) {
        int idx = k * 256 + t;          // ascending per-thread -> strict <
        float v = src[idx];
        sw[idx] = v;
        if (v < bv) { bv = v; bi = idx; }
    }
    __syncthreads();

    // phase 2: 4x bilinear upsample, gemm-faithful scalar arithmetic
    float* od = out + OFF_D + (size_t)bn * 65536;
    float bv2 = 3.0e38f; int bi2 = 0;
    for (int it = 0; it < 16; it++) {
        int T = it * 256 + t;
        int ti = T >> 6, tj = T & 63;
        int yU = (ti > 0) ? ti - 1 : 0;
        int yD = (ti < 63) ? ti + 1 : 63;
        int xL = (tj > 0) ? tj - 1 : 0;
        int xR = (tj < 63) ? tj + 1 : 63;

        float up[3] = { sw[yU * 64 + xL], sw[yU * 64 + tj], sw[yU * 64 + xR] };
        float ce[3] = { sw[ti * 64 + xL], sw[ti * 64 + tj], sw[ti * 64 + xR] };
        float dn[3] = { sw[yD * 64 + xL], sw[yD * 64 + tj], sw[yD * 64 + xR] };

        float vy[4][3];
#pragma unroll
        for (int c3 = 0; c3 < 3; c3++) {
            if (ti == 0) { vy[0][c3] = ce[c3]; vy[1][c3] = ce[c3]; }
            else {
                vy[0][c3] = fmaf(0.625f, ce[c3], __fmul_rn(0.375f, up[c3]));
                vy[1][c3] = fmaf(0.875f, ce[c3], __fmul_rn(0.125f, up[c3]));
            }
            if (ti == 63) { vy[2][c3] = ce[c3]; vy[3][c3] = ce[c3]; }
            else {
                vy[2][c3] = fmaf(0.125f, dn[c3], __fmul_rn(0.875f, ce[c3]));
                vy[3][c3] = fmaf(0.375f, dn[c3], __fmul_rn(0.625f, ce[c3]));
            }
        }
#pragma unroll
        for (int r = 0; r < 4; r++) {
            float vL = vy[r][0], vC = vy[r][1], vR = vy[r][2];
            float o0, o1, o2, o3;
            if (tj == 0) { o0 = vC; o1 = vC; }
            else {
                o0 = fmaf(0.625f, vC, __fmul_rn(0.375f, vL));
                o1 = fmaf(0.875f, vC, __fmul_rn(0.125f, vL));
            }
            if (tj == 63) { o2 = vC; o3 = vC; }
            else {
                o2 = fmaf(0.125f, vR, __fmul_rn(0.875f, vC));
                o3 = fmaf(0.375f, vR, __fmul_rn(0.625f, vC));
            }
            int pbase = (4 * ti + r) * 256 + 4 * tj;
            *reinterpret_cast<float4*>(od + pbase) = make_float4(o0, o1, o2, o3);
            if (o0 < bv2) { bv2 = o0; bi2 = pbase; }
            if (o1 < bv2) { bv2 = o1; bi2 = pbase + 1; }
            if (o2 < bv2) { bv2 = o2; bi2 = pbase + 2; }
            if (o3 < bv2) { bv2 = o3; bi2 = pbase + 3; }
        }
    }

    // deferred reduction 1 (wdist)
    __syncthreads();
    rv[t] = bv; ri[t] = bi;
    __syncthreads();
    for (int s = 128; s > 0; s >>= 1) {
        if (t < s) {
            float v2 = rv[t + s]; int i2 = ri[t + s];
            if (v2 < rv[t] || (v2 == rv[t] && i2 < ri[t])) { rv[t] = v2; ri[t] = i2; }
        }
        __syncthreads();
    }
    const float gmin1 = rv[0];
    const int   idx1  = ri[0];
    __syncthreads();

    // deferred reduction 2 (dist_x4)
    rv[t] = bv2; ri[t] = bi2;
    __syncthreads();
    for (int s = 128; s > 0; s >>= 1) {
        if (t < s) {
            float v2 = rv[t + s]; int i2 = ri[t + s];
            if (v2 < rv[t] || (v2 == rv[t] && i2 < ri[t])) { rv[t] = v2; ri[t] = i2; }
        }
        __syncthreads();
    }

    if (t == 0) {
        int sidx = ri[0];
        bool nonzero = false;
        for (int c = 0; c < CC; c++) nonzero |= (keys[bn * CC + c] != 0.0f);
        bool valid = nonzero && ((int)floorf(gmin1) <= 5);
        s_valid = valid ? 1 : 0;
        int sv = valid ? (sidx >> 8)  : -1;
        int sh = valid ? (sidx & 255) : -1;
        out[OFF_J + bn * 2 + 0] = (float)sv;
        out[OFF_J + bn * 2 + 1] = (float)sh;
        out[OFF_V + bn] = valid ? 1.0f : 0.0f;
    }
    __syncthreads();
    if (t < CC) {
        float nk = s_valid ? q[((size_t)b * CC + t) * HW + idx1]
                           : keys[bn * CC + t];
        out[OFF_K + bn * CC + t] = nk;
    }
}

extern "C" void kernel_launch(void* const* d_in, const int* in_sizes, int n_in,
                              void* d_out, int out_size) {
    const float* q      = (const float*)d_in[0];
    const float* keys   = (const float*)d_in[1];
    const int*   joints = (const int*)  d_in[2];
    float* out = (float*)d_out;

    dim3 gA(16, BB);                   // 1024 blocks per pass
    kA1<<<gA, 256>>>(q, keys);
    kA2<<<gA, 256>>>(q, keys, joints);
    kB<<<BB * NN, 256>>>(q, keys, out);
}

// round 17
// speedup vs baseline: 1.4761x; 1.1968x over previous
#include <cuda_runtime.h>
#include <math.h>

#define BB 64
#define NN 17
#define CC 32
#define HW 4096   // 64*64

#define OFF_J 0           // joints: 64*17*2 = 2176
#define OFF_V 2176        // valid:  64*17   = 1088
#define OFF_K 3264        // new_keys: 64*17*32 = 34816
#define OFF_D 38080       // dist_x4: 64*17*256*256 = 71303168

#define P_BLOCKS 1024     // producers: 16 chunks x 64 b
#define C_BLOCKS (BB*NN)  // consumers: 1088

__device__ float g_wdist[(size_t)BB * NN * HW];
__device__ int   g_done[BB];   // zero-init; self-resetting each launch
__device__ int   g_cons[BB];

// Proven-equal closed form of the 15-move ring weight (validated rounds 11-16)
__device__ __forceinline__ float weight_at(int x, int y, int kx, int ky) {
    int dx = abs(x - kx), dy = abs(y - ky);
    int M = max(dx, dy);
    bool border = (kx == 0) | (kx == 63) | (ky == 0) | (ky == 63);
    if (M == 0) return border ? 0.75f : 10.0f;
    return (M <= 15) ? fmaf(0.25f, (float)M, 0.5f) : 10.0f;
}

// ---------------- Unified producer/consumer kernel ----------------
// Producers (bid < P_BLOCKS) compute wdist; consumers (bid >= P_BLOCKS)
// spin on per-b flags then run the round-14 kB body verbatim. Producers
// occupy the lowest bids -> scheduled first -> no deadlock.
__global__ void __launch_bounds__(256) kU(const float* __restrict__ q,
                                          const float* __restrict__ keys,
                                          const int*   __restrict__ joints,
                                          float* __restrict__ out)
{
    const int bid = blockIdx.x;
    const int t   = threadIdx.x;

    __shared__ float sw[64 * 64];        // consumer tile / (unused by producer)
    __shared__ float rv[256];
    __shared__ int   ri[256];
    __shared__ int   s_valid;

    if (bid < P_BLOCKS) {
        // ================= producer: kA (round-14 arithmetic) =================
        const int b = bid >> 4;
        const int p = (bid & 15) * 256 + t;

        __shared__ __align__(16) float skey[NN][CC];
        __shared__ float sk2[NN];
        __shared__ int   skx[NN], sky[NN];
        if (t < NN * CC / 4)
            reinterpret_cast<float4*>(skey)[t] =
                reinterpret_cast<const float4*>(keys + b * NN * CC)[t];
        __syncthreads();
        if (t < NN) {
            float s = 0.f;   // mul+add sequential, no fma (XLA-faithful)
            for (int c = 0; c < CC; c++) s = __fadd_rn(s, __fmul_rn(skey[t][c], skey[t][c]));
            sk2[t] = s;
            skx[t] = joints[(b * NN + t) * 2 + 0];
            sky[t] = joints[(b * NN + t) * 2 + 1];
        }
        __syncthreads();

        float qv[CC];
        const float* qb = q + (size_t)b * CC * HW + p;
        float q2 = 0.f;
#pragma unroll
        for (int c = 0; c < CC; c++) {
            qv[c] = qb[(size_t)c * HW];
            q2 = __fadd_rn(q2, __fmul_rn(qv[c], qv[c]));
        }

        const int y = p >> 6, x = p & 63;
        float* wout = g_wdist + ((size_t)b * NN) * HW + p;
#pragma unroll 2
        for (int n = 0; n < NN; n++) {
            const float4* k4 = reinterpret_cast<const float4*>(skey[n]);
            float dot = 0.f;   // sequential ascending-c fmaf (gemm-faithful)
#pragma unroll
            for (int c4 = 0; c4 < CC / 4; c4++) {
                float4 kk = k4[c4];
                dot = fmaf(kk.x, qv[4 * c4 + 0], dot);
                dot = fmaf(kk.y, qv[4 * c4 + 1], dot);
                dot = fmaf(kk.z, qv[4 * c4 + 2], dot);
                dot = fmaf(kk.w, qv[4 * c4 + 3], dot);
            }
            float d2 = __fsub_rn(__fadd_rn(q2, sk2[n]), __fmul_rn(2.0f, dot));
            float dist = sqrtf(fmaxf(d2, 0.0f));
            float wm = weight_at(x, y, skx[n], sky[n]);
            wout[(size_t)n * HW] = __fmul_rn(dist, wm);
        }

        __syncthreads();                 // all stores in block done
        if (t == 0) {
            __threadfence();             // publish wdist before signal
            atomicAdd(&g_done[b], 1);
        }
        return;
    }

    // ================= consumer: kB (round-14 body verbatim) =================
    const int bn = bid - P_BLOCKS;
    const int b  = bn / NN;

    if (t == 0) {
        while (atomicAdd(&g_done[b], 0) < 16) __nanosleep(128);
        __threadfence();                 // acquire
    }
    __syncthreads();

    // phase 1: load wdist, per-thread min/argmin (reduction deferred)
    const float* src = g_wdist + (size_t)bn * HW;
    float bv = 3.0e38f; int bi = 0;
    for (int k = 0; k < 16; k++) {
        int idx = k * 256 + t;          // ascending per-thread -> strict <
        float v = src[idx];
        sw[idx] = v;
        if (v < bv) { bv = v; bi = idx; }
    }
    __syncthreads();

    // flag self-reset: 17th consumer of this b zeroes the counters so every
    // launch (incl. graph replays) starts from the same state.
    if (t == 0) {
        int old = atomicAdd(&g_cons[b], 1);
        if (old == NN - 1) {             // last consumer for this b
            atomicExch(&g_done[b], 0);
            atomicExch(&g_cons[b], 0);
        }
    }

    // phase 2: 4x bilinear upsample, gemm-faithful scalar arithmetic
    float* od = out + OFF_D + (size_t)bn * 65536;
    float bv2 = 3.0e38f; int bi2 = 0;
    for (int it = 0; it < 16; it++) {
        int T = it * 256 + t;
        int ti = T >> 6, tj = T & 63;
        int yU = (ti > 0) ? ti - 1 : 0;
        int yD = (ti < 63) ? ti + 1 : 63;
        int xL = (tj > 0) ? tj - 1 : 0;
        int xR = (tj < 63) ? tj + 1 : 63;

        float up[3] = { sw[yU * 64 + xL], sw[yU * 64 + tj], sw[yU * 64 + xR] };
        float ce[3] = { sw[ti * 64 + xL], sw[ti * 64 + tj], sw[ti * 64 + xR] };
        float dn[3] = { sw[yD * 64 + xL], sw[yD * 64 + tj], sw[yD * 64 + xR] };

        float vy[4][3];
#pragma unroll
        for (int c3 = 0; c3 < 3; c3++) {
            if (ti == 0) { vy[0][c3] = ce[c3]; vy[1][c3] = ce[c3]; }
            else {
                vy[0][c3] = fmaf(0.625f, ce[c3], __fmul_rn(0.375f, up[c3]));
                vy[1][c3] = fmaf(0.875f, ce[c3], __fmul_rn(0.125f, up[c3]));
            }
            if (ti == 63) { vy[2][c3] = ce[c3]; vy[3][c3] = ce[c3]; }
            else {
                vy[2][c3] = fmaf(0.125f, dn[c3], __fmul_rn(0.875f, ce[c3]));
                vy[3][c3] = fmaf(0.375f, dn[c3], __fmul_rn(0.625f, ce[c3]));
            }
        }
#pragma unroll
        for (int r = 0; r < 4; r++) {
            float vL = vy[r][0], vC = vy[r][1], vR = vy[r][2];
            float o0, o1, o2, o3;
            if (tj == 0) { o0 = vC; o1 = vC; }
            else {
                o0 = fmaf(0.625f, vC, __fmul_rn(0.375f, vL));
                o1 = fmaf(0.875f, vC, __fmul_rn(0.125f, vL));
            }
            if (tj == 63) { o2 = vC; o3 = vC; }
            else {
                o2 = fmaf(0.125f, vR, __fmul_rn(0.875f, vC));
                o3 = fmaf(0.375f, vR, __fmul_rn(0.625f, vC));
            }
            int pbase = (4 * ti + r) * 256 + 4 * tj;
            *reinterpret_cast<float4*>(od + pbase) = make_float4(o0, o1, o2, o3);
            if (o0 < bv2) { bv2 = o0; bi2 = pbase; }
            if (o1 < bv2) { bv2 = o1; bi2 = pbase + 1; }
            if (o2 < bv2) { bv2 = o2; bi2 = pbase + 2; }
            if (o3 < bv2) { bv2 = o3; bi2 = pbase + 3; }
        }
    }

    // deferred reduction 1 (wdist)
    __syncthreads();
    rv[t] = bv; ri[t] = bi;
    __syncthreads();
    for (int s = 128; s > 0; s >>= 1) {
        if (t < s) {
            float v2 = rv[t + s]; int i2 = ri[t + s];
            if (v2 < rv[t] || (v2 == rv[t] && i2 < ri[t])) { rv[t] = v2; ri[t] = i2; }
        }
        __syncthreads();
    }
    const float gmin1 = rv[0];
    const int   idx1  = ri[0];
    __syncthreads();

    // deferred reduction 2 (dist_x4)
    rv[t] = bv2; ri[t] = bi2;
    __syncthreads();
    for (int s = 128; s > 0; s >>= 1) {
        if (t < s) {
            float v2 = rv[t + s]; int i2 = ri[t + s];
            if (v2 < rv[t] || (v2 == rv[t] && i2 < ri[t])) { rv[t] = v2; ri[t] = i2; }
        }
        __syncthreads();
    }

    if (t == 0) {
        int sidx = ri[0];
        bool nonzero = false;
        for (int c = 0; c < CC; c++) nonzero |= (keys[bn * CC + c] != 0.0f);
        bool valid = nonzero && ((int)floorf(gmin1) <= 5);
        s_valid = valid ? 1 : 0;
        int sv = valid ? (sidx >> 8)  : -1;
        int sh = valid ? (sidx & 255) : -1;
        out[OFF_J + bn * 2 + 0] = (float)sv;
        out[OFF_J + bn * 2 + 1] = (float)sh;
        out[OFF_V + bn] = valid ? 1.0f : 0.0f;
    }
    __syncthreads();
    if (t < CC) {
        float nk = s_valid ? q[((size_t)b * CC + t) * HW + idx1]
                           : keys[bn * CC + t];
        out[OFF_K + bn * CC + t] = nk;
    }
}

extern "C" void kernel_launch(void* const* d_in, const int* in_sizes, int n_in,
                              void* d_out, int out_size) {
    const float* q      = (const float*)d_in[0];
    const float* keys   = (const float*)d_in[1];
    const int*   joints = (const int*)  d_in[2];
    float* out = (float*)d_out;

    kU<<<P_BLOCKS + C_BLOCKS, 256>>>(q, keys, joints, out);
}